// round 13
// baseline (speedup 1.0000x reference)
#include <cuda_runtime.h>
#include <cuda_fp16.h>
#include <cstdint>

#define HID    128
#define KPAD   2048            // padded K (relations)
#define MAXE   16384           // padded entity rows
#define KB     64              // K per pipeline chunk (64 halves = 128 B rows)
#define NCH    (KPAD / KB)     // 32 chunks
#define PITCH  144             // smem row pitch: 128B data + 16B skew (bank-shift 4)
#define ATILE  (128 * PITCH)   // 18432 B per operand tile
#define STG_B  (2 * ATILE)     // A + B per stage
#define NSTAGES 3
#define SMEM_TOT (1024 + NSTAGES * STG_B)

// ---- static device scratch ----
__device__ __half g_S  [MAXE * KPAD];  // dense incidence-value matrix (64 MB)
__device__ __half g_Bt [HID  * KPAD];  // Bt[n][k]: transformed table, transposed
__device__ float  g_Wt [HID * HID];    // W transposed
__device__ float  g_T32[KPAD * HID];   // fp32 T[r][o] before transpose

// ===========================================================================
// helpers
// ===========================================================================
__device__ __forceinline__ uint32_t smem_u32(const void* p) {
    uint32_t a;
    asm("{ .reg .u64 t; cvta.to.shared.u64 t, %1; cvt.u32.u64 %0, t; }"
        : "=r"(a) : "l"(p));
    return a;
}
__device__ __forceinline__ void ldsm_x4(uint32_t& r0, uint32_t& r1,
                                        uint32_t& r2, uint32_t& r3, uint32_t a) {
    asm volatile("ldmatrix.sync.aligned.m8n8.x4.shared.b16 {%0,%1,%2,%3}, [%4];"
                 : "=r"(r0), "=r"(r1), "=r"(r2), "=r"(r3) : "r"(a));
}
__device__ __forceinline__ void mma16816(float* c, const uint32_t* a,
                                         uint32_t b0, uint32_t b1) {
    asm volatile(
        "mma.sync.aligned.m16n8k16.row.col.f32.f16.f16.f32 "
        "{%0,%1,%2,%3}, {%4,%5,%6,%7}, {%8,%9}, {%0,%1,%2,%3};"
        : "+f"(c[0]), "+f"(c[1]), "+f"(c[2]), "+f"(c[3])
        : "r"(a[0]), "r"(a[1]), "r"(a[2]), "r"(a[3]), "r"(b0), "r"(b1));
}
#define MBAR_INIT(a, n) \
    asm volatile("mbarrier.init.shared.b64 [%0], %1;" :: "r"(a), "r"(n) : "memory")
#define MBAR_EXPECT(a, bytes) \
    asm volatile("mbarrier.arrive.expect_tx.shared.b64 _, [%0], %1;" \
                 :: "r"(a), "r"(bytes) : "memory")
#define MBAR_WAIT(a, ph) do {                                                   \
    asm volatile("{ .reg .pred P;\n"                                            \
        "W%=: mbarrier.try_wait.parity.acquire.cta.shared::cta.b64 P, [%0], %1, 0x989680;\n" \
        "@P bra.uni D%=;\n bra.uni W%=;\n D%=: }"                               \
        :: "r"(a), "r"(ph) : "memory");                                         \
} while (0)
__device__ __forceinline__ void bulk_cp(uint32_t dst, const void* src,
                                        uint32_t mbar) {
    asm volatile(
        "cp.async.bulk.shared::cta.global.mbarrier::complete_tx::bytes "
        "[%0], [%1], 128, [%2];"
        :: "r"(dst), "l"(src), "r"(mbar) : "memory");
}

// ===========================================================================
// K1: fused zeroS (blocks 16..) + W transpose (blocks 0..15).
// ===========================================================================
__global__ void __launch_bounds__(256) zero_wtrans_kernel(
    const float* __restrict__ W)
{
    if (blockIdx.x < 16) {
        __shared__ float t[32][33];
        const int tx = threadIdx.x & 31, ty = threadIdx.x >> 5;
        const int bi = (blockIdx.x & 3) * 32;
        const int bo = (blockIdx.x >> 2) * 32;
#pragma unroll
        for (int j = 0; j < 4; j++)
            t[ty + j * 8][tx] = W[(bo + ty + j * 8) * HID + bi + tx];
        __syncthreads();
#pragma unroll
        for (int j = 0; j < 4; j++)
            g_Wt[(bi + ty + j * 8) * HID + bo + tx] = t[tx][ty + j * 8];
    } else {
        const int n16 = (MAXE * KPAD * 2) / 16;
        uint4* p = (uint4*)g_S;
        const uint4 z = make_uint4(0, 0, 0, 0);
        int i = (blockIdx.x - 16) * blockDim.x + threadIdx.x;
        int stride = (gridDim.x - 16) * blockDim.x;
        for (; i < n16; i += stride) p[i] = z;
    }
}

// ===========================================================================
// K2: Transform: T32[r][o] = b[o] + sum_i x[r][i] * Wt[i][o].  Warp/relation.
// ===========================================================================
__global__ void __launch_bounds__(256) transform_kernel(
    const float* __restrict__ rel_features,
    const float* __restrict__ b,
    int R)
{
    __shared__ float xs[8][HID];
    const int wid  = threadIdx.x >> 5;
    const int lane = threadIdx.x & 31;
    const int r    = blockIdx.x * 8 + wid;
    if (r >= R) return;

    ((float4*)xs[wid])[lane] = ((const float4*)(rel_features + (size_t)r * HID))[lane];
    __syncwarp();

    float4 acc = ((const float4*)b)[lane];
    const float4* __restrict__ Wt4 = (const float4*)g_Wt;
#pragma unroll 8
    for (int i = 0; i < HID; i++) {
        float  xi = xs[wid][i];
        float4 w  = Wt4[i * 32 + lane];
        acc.x = fmaf(xi, w.x, acc.x);
        acc.y = fmaf(xi, w.y, acc.y);
        acc.z = fmaf(xi, w.z, acc.z);
        acc.w = fmaf(xi, w.w, acc.w);
    }
    ((float4*)(g_T32 + (size_t)r * HID))[lane] = acc;
}

// ===========================================================================
// K3: fused fill (blocks 256..) + ttrans (blocks 0..255).
// ===========================================================================
__device__ __forceinline__ void fact_red(int h, int t, int r, float v)
{
    unsigned hv = (unsigned)__half_as_ushort(__float2half(v));
    unsigned pk = (r & 1) ? (hv << 16) : hv;
    const int rp = r & ~1;
    asm volatile("red.global.add.noftz.f16x2 [%0], %1;"
                 :: "l"(g_S + (size_t)t * KPAD + rp), "r"(pk) : "memory");
    asm volatile("red.global.add.noftz.f16x2 [%0], %1;"
                 :: "l"(g_S + (size_t)h * KPAD + rp), "r"(pk) : "memory");
}

__global__ void __launch_bounds__(256) fill_ttrans_kernel(
    const int* __restrict__ heads,
    const int* __restrict__ tails,
    const int* __restrict__ rels,
    const float* __restrict__ val,
    int E, int R)
{
    if (blockIdx.x < 256) {
        __shared__ float t[32][33];
        const int tx = threadIdx.x & 31, ty = threadIdx.x >> 5;
        const int r0 = (blockIdx.x & 63) * 32;
        const int o0 = (blockIdx.x >> 6) * 32;
#pragma unroll
        for (int j = 0; j < 4; j++) {
            int r = r0 + ty + j * 8;
            t[ty + j * 8][tx] = (r < R) ? g_T32[(size_t)r * HID + o0 + tx] : 0.f;
        }
        __syncthreads();
#pragma unroll
        for (int j = 0; j < 4; j++)
            g_Bt[(size_t)(o0 + ty + j * 8) * KPAD + r0 + tx] =
                __float2half(t[tx][ty + j * 8]);
        return;
    }

    const int nq = E >> 2;
    const int i  = (blockIdx.x - 256) * blockDim.x + threadIdx.x;
    if (i < nq) {
        const int4   h = __ldcs((const int4*)heads + i);
        const int4   t = __ldcs((const int4*)tails + i);
        const int4   r = __ldcs((const int4*)rels  + i);
        const float4 v = __ldcs((const float4*)val + i);
        fact_red(h.x, t.x, r.x, v.x);
        fact_red(h.y, t.y, r.y, v.y);
        fact_red(h.z, t.z, r.z, v.z);
        fact_red(h.w, t.w, r.w, v.w);
    } else if (i == nq) {
        for (int f = nq * 4; f < E; f++)
            fact_red(__ldcs(heads + f), __ldcs(tails + f),
                     __ldcs(rels + f), __ldcs(val + f));
    }
}

// ===========================================================================
// K4: GEMM out = relu(S @ Bt^T). CTA = 128M x 128N, 256 thr / 8 warps,
// warp tile 32M x 64N, m16n8k16 HMMA.
// 3-stage pipeline fed by cp.async.bulk (128B/op, mbarrier complete_tx).
// smem: [0..48) mbarriers; [1024 + b*STG_B): A tile (pitch 144), then B tile.
// ===========================================================================
__global__ void __launch_bounds__(256) gemm_kernel(
    float* __restrict__ out, int num_ent)
{
    extern __shared__ char smem[];
    const uint32_t sb = smem_u32(smem);

    const int tid  = threadIdx.x;
    const int lane = tid & 31;
    const int wid  = tid >> 5;
    const int m0   = blockIdx.x * 128;
    const int mo   = (wid >> 1) * 32;
    const int no   = (wid & 1) * 64;

    if (tid == 0) {
#pragma unroll
        for (int b = 0; b < NSTAGES; b++) MBAR_INIT(sb + 16 * b, 1);
    }
    __syncthreads();

    float acc[2][8][4];
#pragma unroll
    for (int i = 0; i < 2; i++)
#pragma unroll
        for (int j = 0; j < 8; j++)
#pragma unroll
            for (int k = 0; k < 4; k++) acc[i][j][k] = 0.f;

    auto issue_stage = [&](int s) {
        const int b = s % NSTAGES;
        const uint32_t base = sb + 1024 + b * STG_B;
        const uint32_t mbar = sb + 16 * b;
        if (tid == 0) MBAR_EXPECT(mbar, 32768);
        const int k0 = s * KB;
        if (tid < 128) {
            // A row tid: 128 contiguous bytes of S
            bulk_cp(base + tid * PITCH,
                    g_S + (size_t)(m0 + tid) * KPAD + k0, mbar);
        } else {
            const int r = tid - 128;
            bulk_cp(base + ATILE + r * PITCH,
                    g_Bt + (size_t)r * KPAD + k0, mbar);
        }
    };

    issue_stage(0);
    issue_stage(1);

    for (int s = 0; s < NCH; s++) {
        if (s + 2 < NCH) issue_stage(s + 2);

        const int b = s % NSTAGES;
        MBAR_WAIT(sb + 16 * b, (s / NSTAGES) & 1);
        __syncthreads();

        const uint32_t bA = sb + 1024 + b * STG_B;
        const uint32_t bB = bA + ATILE;

#pragma unroll
        for (int ks = 0; ks < 4; ks++) {
            uint32_t a[2][4];
#pragma unroll
            for (int im = 0; im < 2; im++) {
                int row   = mo + im * 16 + (lane & 15);
                int chunk = ks * 2 + (lane >> 4);
                ldsm_x4(a[im][0], a[im][1], a[im][2], a[im][3],
                        bA + row * PITCH + chunk * 16);
            }
            uint32_t br[4][4];
#pragma unroll
            for (int jn = 0; jn < 4; jn++) {
                int nrow  = no + jn * 16 + (lane & 7) + (((lane >> 3) & 1) << 3);
                int chunk = ks * 2 + (lane >> 4);
                ldsm_x4(br[jn][0], br[jn][1], br[jn][2], br[jn][3],
                        bB + nrow * PITCH + chunk * 16);
            }
#pragma unroll
            for (int im = 0; im < 2; im++)
#pragma unroll
                for (int jn = 0; jn < 4; jn++) {
                    mma16816(acc[im][jn * 2 + 0], a[im], br[jn][0], br[jn][2]);
                    mma16816(acc[im][jn * 2 + 1], a[im], br[jn][1], br[jn][3]);
                }
        }
        __syncthreads();
    }

    // epilogue: ReLU + store
#pragma unroll
    for (int im = 0; im < 2; im++) {
        int row0 = m0 + mo + im * 16 + (lane >> 2);
#pragma unroll
        for (int j = 0; j < 8; j++) {
            int col = no + j * 8 + (lane & 3) * 2;
            float* c = acc[im][j];
            if (row0 < num_ent) {
                float2 v = make_float2(fmaxf(c[0], 0.f), fmaxf(c[1], 0.f));
                *(float2*)(out + (size_t)row0 * HID + col) = v;
            }
            if (row0 + 8 < num_ent) {
                float2 v = make_float2(fmaxf(c[2], 0.f), fmaxf(c[3], 0.f));
                *(float2*)(out + (size_t)(row0 + 8) * HID + col) = v;
            }
        }
    }
}

// ===========================================================================
// Inputs: 0 local_entity(unused) 1 heads 2 tails 3 rels 4 val
//         5 rel_features[R,128] 6 W[128,128] 7 b[128]  -> out f32 [num_ent,128]
// ===========================================================================
extern "C" void kernel_launch(void* const* d_in, const int* in_sizes, int n_in,
                              void* d_out, int out_size)
{
    const int*   heads = (const int*)  d_in[1];
    const int*   tails = (const int*)  d_in[2];
    const int*   rels  = (const int*)  d_in[3];
    const float* val   = (const float*)d_in[4];
    const float* rel_f = (const float*)d_in[5];
    const float* W     = (const float*)d_in[6];
    const float* b     = (const float*)d_in[7];
    float*       out   = (float*)d_out;

    const int E       = in_sizes[1];
    const int R       = in_sizes[5] / HID;
    const int num_ent = out_size / HID;
    const int mtiles  = (num_ent + 127) / 128;

    cudaFuncSetAttribute(gemm_kernel,
                         cudaFuncAttributeMaxDynamicSharedMemorySize, SMEM_TOT);

    zero_wtrans_kernel<<<16 + 2048, 256>>>(W);
    transform_kernel<<<(R + 7) / 8, 256>>>(rel_f, b, R);
    const int fillBlocks = (E / 4 + 1 + 255) / 256;
    fill_ttrans_kernel<<<256 + fillBlocks, 256>>>(heads, tails, rels, val, E, R);
    gemm_kernel<<<mtiles, 256, SMEM_TOT>>>(out, num_ent);
}

// round 14
// speedup vs baseline: 1.2941x; 1.2941x over previous
#include <cuda_runtime.h>
#include <cuda_fp16.h>
#include <cstdint>

#define HID    128
#define KPAD   2048            // padded K (relations)
#define MAXE   16384           // padded entity rows
#define KB     64              // K per pipeline chunk (64 halves = 128 B rows)
#define NCH    (KPAD / KB)     // 32 chunks
#define STG_BYTES 32768        // A(16KB)+B(16KB) per stage
#define NSTAGES   3
#define SMEM_TOT  (NSTAGES * STG_BYTES)

// ---- static device scratch ----
__device__ __half g_S  [MAXE * KPAD];  // dense incidence-value matrix (64 MB)
__device__ __half g_Bt [HID  * KPAD];  // Bt[n][k]: transformed table, transposed
__device__ float  g_Wt [HID * HID];    // W transposed
__device__ float  g_T32[KPAD * HID];   // fp32 T[r][o] before transpose

// ===========================================================================
// helpers
// ===========================================================================
__device__ __forceinline__ uint32_t smem_u32(const void* p) {
    uint32_t a;
    asm("{ .reg .u64 t; cvta.to.shared.u64 t, %1; cvt.u32.u64 %0, t; }"
        : "=r"(a) : "l"(p));
    return a;
}
__device__ __forceinline__ void cp_async16(uint32_t dst, const void* src) {
    asm volatile("cp.async.cg.shared.global [%0], [%1], 16;"
                 :: "r"(dst), "l"(src) : "memory");
}
__device__ __forceinline__ void ldsm_x4(uint32_t& r0, uint32_t& r1,
                                        uint32_t& r2, uint32_t& r3, uint32_t a) {
    asm volatile("ldmatrix.sync.aligned.m8n8.x4.shared.b16 {%0,%1,%2,%3}, [%4];"
                 : "=r"(r0), "=r"(r1), "=r"(r2), "=r"(r3) : "r"(a));
}
__device__ __forceinline__ void mma16816(float* c, const uint32_t* a,
                                         uint32_t b0, uint32_t b1) {
    asm volatile(
        "mma.sync.aligned.m16n8k16.row.col.f32.f16.f16.f32 "
        "{%0,%1,%2,%3}, {%4,%5,%6,%7}, {%8,%9}, {%0,%1,%2,%3};"
        : "+f"(c[0]), "+f"(c[1]), "+f"(c[2]), "+f"(c[3])
        : "r"(a[0]), "r"(a[1]), "r"(a[2]), "r"(a[3]), "r"(b0), "r"(b1));
}
#define SWZ_OFF(row, chunk) (((row) * 128) + ((((chunk) ^ ((row) & 7))) << 4))

// ===========================================================================
// K1: fused zeroS (blocks 16..) + W transpose (blocks 0..15).
// ===========================================================================
__global__ void __launch_bounds__(256) zero_wtrans_kernel(
    const float* __restrict__ W)
{
    if (blockIdx.x < 16) {
        __shared__ float t[32][33];
        const int tx = threadIdx.x & 31, ty = threadIdx.x >> 5;
        const int bi = (blockIdx.x & 3) * 32;
        const int bo = (blockIdx.x >> 2) * 32;
#pragma unroll
        for (int j = 0; j < 4; j++)
            t[ty + j * 8][tx] = W[(bo + ty + j * 8) * HID + bi + tx];
        __syncthreads();
#pragma unroll
        for (int j = 0; j < 4; j++)
            g_Wt[(bi + ty + j * 8) * HID + bo + tx] = t[tx][ty + j * 8];
    } else {
        const int n16 = (MAXE * KPAD * 2) / 16;
        uint4* p = (uint4*)g_S;
        const uint4 z = make_uint4(0, 0, 0, 0);
        int i = (blockIdx.x - 16) * blockDim.x + threadIdx.x;
        int stride = (gridDim.x - 16) * blockDim.x;
        for (; i < n16; i += stride) p[i] = z;
    }
}

// ===========================================================================
// K2: Transform: T32[r][o] = b[o] + sum_i x[r][i] * Wt[i][o].  Warp/relation.
// ===========================================================================
__global__ void __launch_bounds__(256) transform_kernel(
    const float* __restrict__ rel_features,
    const float* __restrict__ b,
    int R)
{
    __shared__ float xs[8][HID];
    const int wid  = threadIdx.x >> 5;
    const int lane = threadIdx.x & 31;
    const int r    = blockIdx.x * 8 + wid;
    if (r >= R) return;

    ((float4*)xs[wid])[lane] = ((const float4*)(rel_features + (size_t)r * HID))[lane];
    __syncwarp();

    float4 acc = ((const float4*)b)[lane];
    const float4* __restrict__ Wt4 = (const float4*)g_Wt;
#pragma unroll 8
    for (int i = 0; i < HID; i++) {
        float  xi = xs[wid][i];
        float4 w  = Wt4[i * 32 + lane];
        acc.x = fmaf(xi, w.x, acc.x);
        acc.y = fmaf(xi, w.y, acc.y);
        acc.z = fmaf(xi, w.z, acc.z);
        acc.w = fmaf(xi, w.w, acc.w);
    }
    ((float4*)(g_T32 + (size_t)r * HID))[lane] = acc;
}

// ===========================================================================
// K3: fused fill (blocks 256..) + ttrans (blocks 0..255).
// fill: NO-RETURN red.global.add.noftz.f16x2 into S.
// ===========================================================================
__device__ __forceinline__ void fact_red(int h, int t, int r, float v)
{
    unsigned hv = (unsigned)__half_as_ushort(__float2half(v));
    unsigned pk = (r & 1) ? (hv << 16) : hv;
    const int rp = r & ~1;
    asm volatile("red.global.add.noftz.f16x2 [%0], %1;"
                 :: "l"(g_S + (size_t)t * KPAD + rp), "r"(pk) : "memory");
    asm volatile("red.global.add.noftz.f16x2 [%0], %1;"
                 :: "l"(g_S + (size_t)h * KPAD + rp), "r"(pk) : "memory");
}

__global__ void __launch_bounds__(256) fill_ttrans_kernel(
    const int* __restrict__ heads,
    const int* __restrict__ tails,
    const int* __restrict__ rels,
    const float* __restrict__ val,
    int E, int R)
{
    if (blockIdx.x < 256) {
        __shared__ float t[32][33];
        const int tx = threadIdx.x & 31, ty = threadIdx.x >> 5;
        const int r0 = (blockIdx.x & 63) * 32;
        const int o0 = (blockIdx.x >> 6) * 32;
#pragma unroll
        for (int j = 0; j < 4; j++) {
            int r = r0 + ty + j * 8;
            t[ty + j * 8][tx] = (r < R) ? g_T32[(size_t)r * HID + o0 + tx] : 0.f;
        }
        __syncthreads();
#pragma unroll
        for (int j = 0; j < 4; j++)
            g_Bt[(size_t)(o0 + ty + j * 8) * KPAD + r0 + tx] =
                __float2half(t[tx][ty + j * 8]);
        return;
    }

    const int nq = E >> 2;
    const int i  = (blockIdx.x - 256) * blockDim.x + threadIdx.x;
    if (i < nq) {
        const int4   h = __ldcs((const int4*)heads + i);
        const int4   t = __ldcs((const int4*)tails + i);
        const int4   r = __ldcs((const int4*)rels  + i);
        const float4 v = __ldcs((const float4*)val + i);
        fact_red(h.x, t.x, r.x, v.x);
        fact_red(h.y, t.y, r.y, v.y);
        fact_red(h.z, t.z, r.z, v.z);
        fact_red(h.w, t.w, r.w, v.w);
    } else if (i == nq) {
        for (int f = nq * 4; f < E; f++)
            fact_red(__ldcs(heads + f), __ldcs(tails + f),
                     __ldcs(rels + f), __ldcs(val + f));
    }
}

// ===========================================================================
// K4: GEMM out = relu(S @ Bt^T). CTA = 128M x 128N, *512* thr / 16 warps,
// warp tile 32M x 32N, m16n8k16 HMMA, 3-stage cp.async (LDGSTS) pipeline.
// 16 warps = 4/SMSP to test LDGSTS issue scaling.
// ===========================================================================
__global__ void __launch_bounds__(512) gemm_kernel(
    float* __restrict__ out, int num_ent)
{
    extern __shared__ char smem[];
    const uint32_t sb = smem_u32(smem);

    const int tid  = threadIdx.x;
    const int lane = tid & 31;
    const int wid  = tid >> 5;
    const int m0   = blockIdx.x * 128;
    const int mo   = (wid >> 2) * 32;     // 4 M groups
    const int no   = (wid & 3) * 32;      // 4 N groups

    float acc[2][4][4];
#pragma unroll
    for (int i = 0; i < 2; i++)
#pragma unroll
        for (int j = 0; j < 4; j++)
#pragma unroll
            for (int k = 0; k < 4; k++) acc[i][j][k] = 0.f;

    auto load_stage = [&](int s, int buf) {
        const int k0 = s * KB;
        const uint32_t base = sb + buf * STG_BYTES;
#pragma unroll
        for (int i = 0; i < 4; i++) {
            int idx = tid + i * 512;          // 0..2047 16B chunks
            int row = (idx >> 3) & 127;       // 0..127 within tile
            int c   = idx & 7;
            if (idx < 1024) {
                cp_async16(base + SWZ_OFF(row, c),
                           g_S + (size_t)(m0 + row) * KPAD + k0 + c * 8);
            } else {
                cp_async16(base + 16384 + SWZ_OFF(row, c),
                           g_Bt + (size_t)row * KPAD + k0 + c * 8);
            }
        }
        asm volatile("cp.async.commit_group;" ::: "memory");
    };

    load_stage(0, 0);
    load_stage(1, 1);

    for (int s = 0; s < NCH; s++) {
        if (s + 2 < NCH) {
            load_stage(s + 2, (s + 2) % NSTAGES);
            asm volatile("cp.async.wait_group 2;" ::: "memory");
        } else if (s + 1 < NCH) {
            asm volatile("cp.async.wait_group 1;" ::: "memory");
        } else {
            asm volatile("cp.async.wait_group 0;" ::: "memory");
        }
        __syncthreads();

        const uint32_t bA = sb + (s % NSTAGES) * STG_BYTES;
        const uint32_t bB = bA + 16384;

#pragma unroll
        for (int ks = 0; ks < 4; ks++) {
            uint32_t a[2][4];
#pragma unroll
            for (int im = 0; im < 2; im++) {
                int row   = mo + im * 16 + (lane & 15);
                int chunk = ks * 2 + (lane >> 4);
                ldsm_x4(a[im][0], a[im][1], a[im][2], a[im][3],
                        bA + SWZ_OFF(row, chunk));
            }
            uint32_t br[2][4];
#pragma unroll
            for (int jn = 0; jn < 2; jn++) {
                int nrow  = no + jn * 16 + (lane & 7) + (((lane >> 3) & 1) << 3);
                int chunk = ks * 2 + (lane >> 4);
                ldsm_x4(br[jn][0], br[jn][1], br[jn][2], br[jn][3],
                        bB + SWZ_OFF(nrow, chunk));
            }
#pragma unroll
            for (int im = 0; im < 2; im++)
#pragma unroll
                for (int jn = 0; jn < 2; jn++) {
                    mma16816(acc[im][jn * 2 + 0], a[im], br[jn][0], br[jn][2]);
                    mma16816(acc[im][jn * 2 + 1], a[im], br[jn][1], br[jn][3]);
                }
        }
        __syncthreads();
    }

    // epilogue: ReLU + store
#pragma unroll
    for (int im = 0; im < 2; im++) {
        int row0 = m0 + mo + im * 16 + (lane >> 2);
#pragma unroll
        for (int j = 0; j < 4; j++) {
            int col = no + j * 8 + (lane & 3) * 2;
            float* c = acc[im][j];
            if (row0 < num_ent) {
                float2 v = make_float2(fmaxf(c[0], 0.f), fmaxf(c[1], 0.f));
                *(float2*)(out + (size_t)row0 * HID + col) = v;
            }
            if (row0 + 8 < num_ent) {
                float2 v = make_float2(fmaxf(c[2], 0.f), fmaxf(c[3], 0.f));
                *(float2*)(out + (size_t)(row0 + 8) * HID + col) = v;
            }
        }
    }
}

// ===========================================================================
// Inputs: 0 local_entity(unused) 1 heads 2 tails 3 rels 4 val
//         5 rel_features[R,128] 6 W[128,128] 7 b[128]  -> out f32 [num_ent,128]
// ===========================================================================
extern "C" void kernel_launch(void* const* d_in, const int* in_sizes, int n_in,
                              void* d_out, int out_size)
{
    const int*   heads = (const int*)  d_in[1];
    const int*   tails = (const int*)  d_in[2];
    const int*   rels  = (const int*)  d_in[3];
    const float* val   = (const float*)d_in[4];
    const float* rel_f = (const float*)d_in[5];
    const float* W     = (const float*)d_in[6];
    const float* b     = (const float*)d_in[7];
    float*       out   = (float*)d_out;

    const int E       = in_sizes[1];
    const int R       = in_sizes[5] / HID;
    const int num_ent = out_size / HID;
    const int mtiles  = (num_ent + 127) / 128;

    cudaFuncSetAttribute(gemm_kernel,
                         cudaFuncAttributeMaxDynamicSharedMemorySize, SMEM_TOT);

    zero_wtrans_kernel<<<16 + 2048, 256>>>(W);
    transform_kernel<<<(R + 7) / 8, 256>>>(rel_f, b, R);
    const int fillBlocks = (E / 4 + 1 + 255) / 256;
    fill_ttrans_kernel<<<256 + fillBlocks, 256>>>(heads, tails, rels, val, E, R);
    gemm_kernel<<<mtiles, 512, SMEM_TOT>>>(out, num_ent);
}

// round 15
// speedup vs baseline: 1.3221x; 1.0217x over previous
#include <cuda_runtime.h>
#include <cuda_fp16.h>
#include <cstdint>

#define HID    128
#define KPAD   2048            // padded K (relations)
#define MAXE   16384           // padded entity rows
#define KB     64              // K per pipeline chunk (64 halves = 128 B rows)
#define NCH    (KPAD / KB)     // 32 chunks
#define MT     64              // M rows per CTA tile
#define STG_BYTES (8192 + 16384)   // A(8KB) + B(16KB) per stage
#define NSTAGES   3
#define SMEM_TOT  (NSTAGES * STG_BYTES)   // 72 KB -> 2-3 CTAs/SM

// ---- static device scratch ----
__device__ __half g_S  [MAXE * KPAD];  // dense incidence-value matrix (64 MB)
__device__ __half g_Bt [HID  * KPAD];  // Bt[n][k]: transformed table, transposed
__device__ float  g_Wt [HID * HID];    // W transposed
__device__ float  g_T32[KPAD * HID];   // fp32 T[r][o] before transpose

// ===========================================================================
// helpers
// ===========================================================================
__device__ __forceinline__ uint32_t smem_u32(const void* p) {
    uint32_t a;
    asm("{ .reg .u64 t; cvta.to.shared.u64 t, %1; cvt.u32.u64 %0, t; }"
        : "=r"(a) : "l"(p));
    return a;
}
__device__ __forceinline__ void cp_async16(uint32_t dst, const void* src) {
    asm volatile("cp.async.cg.shared.global [%0], [%1], 16;"
                 :: "r"(dst), "l"(src) : "memory");
}
__device__ __forceinline__ void ldsm_x4(uint32_t& r0, uint32_t& r1,
                                        uint32_t& r2, uint32_t& r3, uint32_t a) {
    asm volatile("ldmatrix.sync.aligned.m8n8.x4.shared.b16 {%0,%1,%2,%3}, [%4];"
                 : "=r"(r0), "=r"(r1), "=r"(r2), "=r"(r3) : "r"(a));
}
__device__ __forceinline__ void mma16816(float* c, const uint32_t* a,
                                         uint32_t b0, uint32_t b1) {
    asm volatile(
        "mma.sync.aligned.m16n8k16.row.col.f32.f16.f16.f32 "
        "{%0,%1,%2,%3}, {%4,%5,%6,%7}, {%8,%9}, {%0,%1,%2,%3};"
        : "+f"(c[0]), "+f"(c[1]), "+f"(c[2]), "+f"(c[3])
        : "r"(a[0]), "r"(a[1]), "r"(a[2]), "r"(a[3]), "r"(b0), "r"(b1));
}
#define SWZ_OFF(row, chunk) (((row) * 128) + ((((chunk) ^ ((row) & 7))) << 4))

// ===========================================================================
// K1: fused zeroS (blocks 16..) + W transpose (blocks 0..15).
// ===========================================================================
__global__ void __launch_bounds__(256) zero_wtrans_kernel(
    const float* __restrict__ W)
{
    if (blockIdx.x < 16) {
        __shared__ float t[32][33];
        const int tx = threadIdx.x & 31, ty = threadIdx.x >> 5;
        const int bi = (blockIdx.x & 3) * 32;
        const int bo = (blockIdx.x >> 2) * 32;
#pragma unroll
        for (int j = 0; j < 4; j++)
            t[ty + j * 8][tx] = W[(bo + ty + j * 8) * HID + bi + tx];
        __syncthreads();
#pragma unroll
        for (int j = 0; j < 4; j++)
            g_Wt[(bi + ty + j * 8) * HID + bo + tx] = t[tx][ty + j * 8];
    } else {
        const int n16 = (MAXE * KPAD * 2) / 16;
        uint4* p = (uint4*)g_S;
        const uint4 z = make_uint4(0, 0, 0, 0);
        int i = (blockIdx.x - 16) * blockDim.x + threadIdx.x;
        int stride = (gridDim.x - 16) * blockDim.x;
        for (; i < n16; i += stride) p[i] = z;
    }
}

// ===========================================================================
// K2: Transform: T32[r][o] = b[o] + sum_i x[r][i] * Wt[i][o].  Warp/relation.
// ===========================================================================
__global__ void __launch_bounds__(256) transform_kernel(
    const float* __restrict__ rel_features,
    const float* __restrict__ b,
    int R)
{
    __shared__ float xs[8][HID];
    const int wid  = threadIdx.x >> 5;
    const int lane = threadIdx.x & 31;
    const int r    = blockIdx.x * 8 + wid;
    if (r >= R) return;

    ((float4*)xs[wid])[lane] = ((const float4*)(rel_features + (size_t)r * HID))[lane];
    __syncwarp();

    float4 acc = ((const float4*)b)[lane];
    const float4* __restrict__ Wt4 = (const float4*)g_Wt;
#pragma unroll 8
    for (int i = 0; i < HID; i++) {
        float  xi = xs[wid][i];
        float4 w  = Wt4[i * 32 + lane];
        acc.x = fmaf(xi, w.x, acc.x);
        acc.y = fmaf(xi, w.y, acc.y);
        acc.z = fmaf(xi, w.z, acc.z);
        acc.w = fmaf(xi, w.w, acc.w);
    }
    ((float4*)(g_T32 + (size_t)r * HID))[lane] = acc;
}

// ===========================================================================
// K3: fused fill (blocks 256..) + ttrans (blocks 0..255).
// fill: NO-RETURN red.global.add.noftz.f16x2 into S.
// ===========================================================================
__device__ __forceinline__ void fact_red(int h, int t, int r, float v)
{
    unsigned hv = (unsigned)__half_as_ushort(__float2half(v));
    unsigned pk = (r & 1) ? (hv << 16) : hv;
    const int rp = r & ~1;
    asm volatile("red.global.add.noftz.f16x2 [%0], %1;"
                 :: "l"(g_S + (size_t)t * KPAD + rp), "r"(pk) : "memory");
    asm volatile("red.global.add.noftz.f16x2 [%0], %1;"
                 :: "l"(g_S + (size_t)h * KPAD + rp), "r"(pk) : "memory");
}

__global__ void __launch_bounds__(256) fill_ttrans_kernel(
    const int* __restrict__ heads,
    const int* __restrict__ tails,
    const int* __restrict__ rels,
    const float* __restrict__ val,
    int E, int R)
{
    if (blockIdx.x < 256) {
        __shared__ float t[32][33];
        const int tx = threadIdx.x & 31, ty = threadIdx.x >> 5;
        const int r0 = (blockIdx.x & 63) * 32;
        const int o0 = (blockIdx.x >> 6) * 32;
#pragma unroll
        for (int j = 0; j < 4; j++) {
            int r = r0 + ty + j * 8;
            t[ty + j * 8][tx] = (r < R) ? g_T32[(size_t)r * HID + o0 + tx] : 0.f;
        }
        __syncthreads();
#pragma unroll
        for (int j = 0; j < 4; j++)
            g_Bt[(size_t)(o0 + ty + j * 8) * KPAD + r0 + tx] =
                __float2half(t[tx][ty + j * 8]);
        return;
    }

    const int nq = E >> 2;
    const int i  = (blockIdx.x - 256) * blockDim.x + threadIdx.x;
    if (i < nq) {
        const int4   h = __ldcs((const int4*)heads + i);
        const int4   t = __ldcs((const int4*)tails + i);
        const int4   r = __ldcs((const int4*)rels  + i);
        const float4 v = __ldcs((const float4*)val + i);
        fact_red(h.x, t.x, r.x, v.x);
        fact_red(h.y, t.y, r.y, v.y);
        fact_red(h.z, t.z, r.z, v.z);
        fact_red(h.w, t.w, r.w, v.w);
    } else if (i == nq) {
        for (int f = nq * 4; f < E; f++)
            fact_red(__ldcs(heads + f), __ldcs(tails + f),
                     __ldcs(rels + f), __ldcs(val + f));
    }
}

// ===========================================================================
// K4: GEMM out = relu(S @ Bt^T). CTA = 64M x 128N tile, 128 thr / 4 warps,
// warp tile 32M x 64N, m16n8k16 HMMA, 3-stage cp.async pipeline.
// 24 KB/stage, 72 KB total -> 2-3 CTAs/SM for latency hiding.
// smem stage layout: A (64 rows x 128B) then B (128 rows x 128B).
// ===========================================================================
__global__ void __launch_bounds__(128) gemm_kernel(
    float* __restrict__ out, int num_ent)
{
    extern __shared__ char smem[];
    const uint32_t sb = smem_u32(smem);

    const int tid  = threadIdx.x;
    const int lane = tid & 31;
    const int wid  = tid >> 5;
    const int m0   = blockIdx.x * MT;
    const int mo   = (wid >> 1) * 32;     // 0 or 32 within 64-row tile
    const int no   = (wid & 1) * 64;      // 0 or 64

    float acc[2][8][4];
#pragma unroll
    for (int i = 0; i < 2; i++)
#pragma unroll
        for (int j = 0; j < 8; j++)
#pragma unroll
            for (int k = 0; k < 4; k++) acc[i][j][k] = 0.f;

    auto load_stage = [&](int s, int buf) {
        const int k0 = s * KB;
        const uint32_t bA = sb + buf * STG_BYTES;       // 64 x 128B
        const uint32_t bB = bA + 8192;                  // 128 x 128B
        // A: 512 chunks; B: 1024 chunks; 12 per thread
#pragma unroll
        for (int i = 0; i < 4; i++) {
            int idx = tid + i * 128;          // 0..511
            int row = idx >> 3, c = idx & 7;
            cp_async16(bA + SWZ_OFF(row, c),
                       g_S + (size_t)(m0 + row) * KPAD + k0 + c * 8);
        }
#pragma unroll
        for (int i = 0; i < 8; i++) {
            int idx = tid + i * 128;          // 0..1023
            int row = idx >> 3, c = idx & 7;
            cp_async16(bB + SWZ_OFF(row, c),
                       g_Bt + (size_t)row * KPAD + k0 + c * 8);
        }
        asm volatile("cp.async.commit_group;" ::: "memory");
    };

    load_stage(0, 0);
    load_stage(1, 1);

    for (int s = 0; s < NCH; s++) {
        if (s + 2 < NCH) {
            load_stage(s + 2, (s + 2) % NSTAGES);
            asm volatile("cp.async.wait_group 2;" ::: "memory");
        } else if (s + 1 < NCH) {
            asm volatile("cp.async.wait_group 1;" ::: "memory");
        } else {
            asm volatile("cp.async.wait_group 0;" ::: "memory");
        }
        __syncthreads();

        const uint32_t bA = sb + (s % NSTAGES) * STG_BYTES;
        const uint32_t bB = bA + 8192;

#pragma unroll
        for (int ks = 0; ks < 4; ks++) {
            uint32_t a[2][4];
#pragma unroll
            for (int im = 0; im < 2; im++) {
                int row   = mo + im * 16 + (lane & 15);
                int chunk = ks * 2 + (lane >> 4);
                ldsm_x4(a[im][0], a[im][1], a[im][2], a[im][3],
                        bA + SWZ_OFF(row, chunk));
            }
            uint32_t br[4][4];
#pragma unroll
            for (int jn = 0; jn < 4; jn++) {
                int nrow  = no + jn * 16 + (lane & 7) + (((lane >> 3) & 1) << 3);
                int chunk = ks * 2 + (lane >> 4);
                ldsm_x4(br[jn][0], br[jn][1], br[jn][2], br[jn][3],
                        bB + SWZ_OFF(nrow, chunk));
            }
#pragma unroll
            for (int im = 0; im < 2; im++)
#pragma unroll
                for (int jn = 0; jn < 4; jn++) {
                    mma16816(acc[im][jn * 2 + 0], a[im], br[jn][0], br[jn][2]);
                    mma16816(acc[im][jn * 2 + 1], a[im], br[jn][1], br[jn][3]);
                }
        }
        __syncthreads();
    }

    // epilogue: ReLU + store
#pragma unroll
    for (int im = 0; im < 2; im++) {
        int row0 = m0 + mo + im * 16 + (lane >> 2);
#pragma unroll
        for (int j = 0; j < 8; j++) {
            int col = no + j * 8 + (lane & 3) * 2;
            float* c = acc[im][j];
            if (row0 < num_ent) {
                float2 v = make_float2(fmaxf(c[0], 0.f), fmaxf(c[1], 0.f));
                *(float2*)(out + (size_t)row0 * HID + col) = v;
            }
            if (row0 + 8 < num_ent) {
                float2 v = make_float2(fmaxf(c[2], 0.f), fmaxf(c[3], 0.f));
                *(float2*)(out + (size_t)(row0 + 8) * HID + col) = v;
            }
        }
    }
}

// ===========================================================================
// Inputs: 0 local_entity(unused) 1 heads 2 tails 3 rels 4 val
//         5 rel_features[R,128] 6 W[128,128] 7 b[128]  -> out f32 [num_ent,128]
// ===========================================================================
extern "C" void kernel_launch(void* const* d_in, const int* in_sizes, int n_in,
                              void* d_out, int out_size)
{
    const int*   heads = (const int*)  d_in[1];
    const int*   tails = (const int*)  d_in[2];
    const int*   rels  = (const int*)  d_in[3];
    const float* val   = (const float*)d_in[4];
    const float* rel_f = (const float*)d_in[5];
    const float* W     = (const float*)d_in[6];
    const float* b     = (const float*)d_in[7];
    float*       out   = (float*)d_out;

    const int E       = in_sizes[1];
    const int R       = in_sizes[5] / HID;
    const int num_ent = out_size / HID;
    const int mtiles  = (num_ent + MT - 1) / MT;

    cudaFuncSetAttribute(gemm_kernel,
                         cudaFuncAttributeMaxDynamicSharedMemorySize, SMEM_TOT);

    zero_wtrans_kernel<<<16 + 2048, 256>>>(W);
    transform_kernel<<<(R + 7) / 8, 256>>>(rel_f, b, R);
    const int fillBlocks = (E / 4 + 1 + 255) / 256;
    fill_ttrans_kernel<<<256 + fillBlocks, 256>>>(heads, tails, rels, val, E, R);
    gemm_kernel<<<mtiles, 128, SMEM_TOT>>>(out, num_ent);
}

// round 16
// speedup vs baseline: 1.3257x; 1.0027x over previous
#include <cuda_runtime.h>
#include <cuda_fp16.h>
#include <cstdint>

#define HID    128
#define KPAD   2048            // padded K (relations)
#define MAXE   16384           // padded entity rows
#define KB     64              // K per pipeline chunk (64 halves = 128 B rows)
#define NCH    (KPAD / KB)     // 32 chunks
#define THALF  8192            // halves per (tile,chunk) block: 128 rows x 64
#define STG_BYTES 32768        // A(16KB)+B(16KB) per stage
#define NSTAGES   3
#define SMEM_TOT  (NSTAGES * STG_BYTES)

// ---- static device scratch ----
// S is (tile,chunk)-tiled: S[(e>>7)][(r>>6)][e&127][r&63], fp16.
// Each 16KB block is contiguous -> GEMM stages stream linearly from DRAM.
__device__ __half g_S  [MAXE * KPAD];  // 64 MB
__device__ __half g_Bt [HID  * KPAD];  // Bt[n][k]: transformed table, transposed
__device__ float  g_Wt [HID * HID];    // W transposed
__device__ float  g_T32[KPAD * HID];   // fp32 T[r][o] before transpose

// ===========================================================================
// helpers
// ===========================================================================
__device__ __forceinline__ uint32_t smem_u32(const void* p) {
    uint32_t a;
    asm("{ .reg .u64 t; cvta.to.shared.u64 t, %1; cvt.u32.u64 %0, t; }"
        : "=r"(a) : "l"(p));
    return a;
}
__device__ __forceinline__ void cp_async16(uint32_t dst, const void* src) {
    asm volatile("cp.async.cg.shared.global [%0], [%1], 16;"
                 :: "r"(dst), "l"(src) : "memory");
}
__device__ __forceinline__ void ldsm_x4(uint32_t& r0, uint32_t& r1,
                                        uint32_t& r2, uint32_t& r3, uint32_t a) {
    asm volatile("ldmatrix.sync.aligned.m8n8.x4.shared.b16 {%0,%1,%2,%3}, [%4];"
                 : "=r"(r0), "=r"(r1), "=r"(r2), "=r"(r3) : "r"(a));
}
__device__ __forceinline__ void mma16816(float* c, const uint32_t* a,
                                         uint32_t b0, uint32_t b1) {
    asm volatile(
        "mma.sync.aligned.m16n8k16.row.col.f32.f16.f16.f32 "
        "{%0,%1,%2,%3}, {%4,%5,%6,%7}, {%8,%9}, {%0,%1,%2,%3};"
        : "+f"(c[0]), "+f"(c[1]), "+f"(c[2]), "+f"(c[3])
        : "r"(a[0]), "r"(a[1]), "r"(a[2]), "r"(a[3]), "r"(b0), "r"(b1));
}
#define SWZ_OFF(row, chunk) (((row) * 128) + ((((chunk) ^ ((row) & 7))) << 4))

// ===========================================================================
// K1: fused zeroS (blocks 16..) + W transpose (blocks 0..15).
// ===========================================================================
__global__ void __launch_bounds__(256) zero_wtrans_kernel(
    const float* __restrict__ W)
{
    if (blockIdx.x < 16) {
        __shared__ float t[32][33];
        const int tx = threadIdx.x & 31, ty = threadIdx.x >> 5;
        const int bi = (blockIdx.x & 3) * 32;
        const int bo = (blockIdx.x >> 2) * 32;
#pragma unroll
        for (int j = 0; j < 4; j++)
            t[ty + j * 8][tx] = W[(bo + ty + j * 8) * HID + bi + tx];
        __syncthreads();
#pragma unroll
        for (int j = 0; j < 4; j++)
            g_Wt[(bi + ty + j * 8) * HID + bo + tx] = t[tx][ty + j * 8];
    } else {
        const int n16 = (MAXE * KPAD * 2) / 16;
        uint4* p = (uint4*)g_S;
        const uint4 z = make_uint4(0, 0, 0, 0);
        int i = (blockIdx.x - 16) * blockDim.x + threadIdx.x;
        int stride = (gridDim.x - 16) * blockDim.x;
        for (; i < n16; i += stride) p[i] = z;
    }
}

// ===========================================================================
// K2: Transform: T32[r][o] = b[o] + sum_i x[r][i] * Wt[i][o].  Warp/relation.
// ===========================================================================
__global__ void __launch_bounds__(256) transform_kernel(
    const float* __restrict__ rel_features,
    const float* __restrict__ b,
    int R)
{
    __shared__ float xs[8][HID];
    const int wid  = threadIdx.x >> 5;
    const int lane = threadIdx.x & 31;
    const int r    = blockIdx.x * 8 + wid;
    if (r >= R) return;

    ((float4*)xs[wid])[lane] = ((const float4*)(rel_features + (size_t)r * HID))[lane];
    __syncwarp();

    float4 acc = ((const float4*)b)[lane];
    const float4* __restrict__ Wt4 = (const float4*)g_Wt;
#pragma unroll 8
    for (int i = 0; i < HID; i++) {
        float  xi = xs[wid][i];
        float4 w  = Wt4[i * 32 + lane];
        acc.x = fmaf(xi, w.x, acc.x);
        acc.y = fmaf(xi, w.y, acc.y);
        acc.z = fmaf(xi, w.z, acc.z);
        acc.w = fmaf(xi, w.w, acc.w);
    }
    ((float4*)(g_T32 + (size_t)r * HID))[lane] = acc;
}

// ===========================================================================
// K3: fused fill (blocks 256..) + ttrans (blocks 0..255).
// fill: NO-RETURN red.global.add.noftz.f16x2 into TILED S.
//   addr(e, r) = ((e>>7)*NCH + (r>>6))*THALF + (e&127)*64 + (r&63)
// ===========================================================================
__device__ __forceinline__ void fact_red(int h, int t, int r, float v)
{
    unsigned hv = (unsigned)__half_as_ushort(__float2half(v));
    unsigned pk = (r & 1) ? (hv << 16) : hv;
    const int c  = r >> 6;
    const int rl = (r & 63) & ~1;
    asm volatile("red.global.add.noftz.f16x2 [%0], %1;"
        :: "l"(g_S + (size_t)((t >> 7) * NCH + c) * THALF + (t & 127) * 64 + rl),
           "r"(pk) : "memory");
    asm volatile("red.global.add.noftz.f16x2 [%0], %1;"
        :: "l"(g_S + (size_t)((h >> 7) * NCH + c) * THALF + (h & 127) * 64 + rl),
           "r"(pk) : "memory");
}

__global__ void __launch_bounds__(256) fill_ttrans_kernel(
    const int* __restrict__ heads,
    const int* __restrict__ tails,
    const int* __restrict__ rels,
    const float* __restrict__ val,
    int E, int R)
{
    if (blockIdx.x < 256) {
        __shared__ float t[32][33];
        const int tx = threadIdx.x & 31, ty = threadIdx.x >> 5;
        const int r0 = (blockIdx.x & 63) * 32;
        const int o0 = (blockIdx.x >> 6) * 32;
#pragma unroll
        for (int j = 0; j < 4; j++) {
            int r = r0 + ty + j * 8;
            t[ty + j * 8][tx] = (r < R) ? g_T32[(size_t)r * HID + o0 + tx] : 0.f;
        }
        __syncthreads();
#pragma unroll
        for (int j = 0; j < 4; j++)
            g_Bt[(size_t)(o0 + ty + j * 8) * KPAD + r0 + tx] =
                __float2half(t[tx][ty + j * 8]);
        return;
    }

    const int nq = E >> 2;
    const int i  = (blockIdx.x - 256) * blockDim.x + threadIdx.x;
    if (i < nq) {
        const int4   h = __ldcs((const int4*)heads + i);
        const int4   t = __ldcs((const int4*)tails + i);
        const int4   r = __ldcs((const int4*)rels  + i);
        const float4 v = __ldcs((const float4*)val + i);
        fact_red(h.x, t.x, r.x, v.x);
        fact_red(h.y, t.y, r.y, v.y);
        fact_red(h.z, t.z, r.z, v.z);
        fact_red(h.w, t.w, r.w, v.w);
    } else if (i == nq) {
        for (int f = nq * 4; f < E; f++)
            fact_red(__ldcs(heads + f), __ldcs(tails + f),
                     __ldcs(rels + f), __ldcs(val + f));
    }
}

// ===========================================================================
// K4: GEMM out = relu(S @ Bt^T). CTA = 128M x 128N, 256 thr / 8 warps,
// warp tile 32M x 64N, m16n8k16 HMMA, 3-stage cp.async pipeline.
// A feed: stage s reads ONE CONTIGUOUS 16KB block (tiled S layout).
// ===========================================================================
__global__ void __launch_bounds__(256) gemm_kernel(
    float* __restrict__ out, int num_ent)
{
    extern __shared__ char smem[];
    const uint32_t sb = smem_u32(smem);

    const int tid  = threadIdx.x;
    const int lane = tid & 31;
    const int wid  = tid >> 5;
    const int m0   = blockIdx.x * 128;
    const int mo   = (wid >> 1) * 32;
    const int no   = (wid & 1) * 64;

    float acc[2][8][4];
#pragma unroll
    for (int i = 0; i < 2; i++)
#pragma unroll
        for (int j = 0; j < 8; j++)
#pragma unroll
            for (int k = 0; k < 4; k++) acc[i][j][k] = 0.f;

    auto load_stage = [&](int s, int buf) {
        const int k0 = s * KB;
        const uint32_t bA = sb + buf * STG_BYTES;
        const uint32_t bB = bA + 16384;
        // A: contiguous 16KB block for (tile=blockIdx.x, chunk=s)
        const __half* __restrict__ aSrc =
            g_S + (size_t)(blockIdx.x * NCH + s) * THALF;
#pragma unroll
        for (int i = 0; i < 4; i++) {
            int idx = tid + i * 256;          // 0..1023 16B chunks
            int row = idx >> 3, c = idx & 7;
            cp_async16(bA + SWZ_OFF(row, c), aSrc + idx * 8);
            cp_async16(bB + SWZ_OFF(row, c),
                       g_Bt + (size_t)row * KPAD + k0 + c * 8);
        }
        asm volatile("cp.async.commit_group;" ::: "memory");
    };

    load_stage(0, 0);
    load_stage(1, 1);

    for (int s = 0; s < NCH; s++) {
        if (s + 2 < NCH) {
            load_stage(s + 2, (s + 2) % NSTAGES);
            asm volatile("cp.async.wait_group 2;" ::: "memory");
        } else if (s + 1 < NCH) {
            asm volatile("cp.async.wait_group 1;" ::: "memory");
        } else {
            asm volatile("cp.async.wait_group 0;" ::: "memory");
        }
        __syncthreads();

        const uint32_t bA = sb + (s % NSTAGES) * STG_BYTES;
        const uint32_t bB = bA + 16384;

#pragma unroll
        for (int ks = 0; ks < 4; ks++) {
            uint32_t a[2][4];
#pragma unroll
            for (int im = 0; im < 2; im++) {
                int row   = mo + im * 16 + (lane & 15);
                int chunk = ks * 2 + (lane >> 4);
                ldsm_x4(a[im][0], a[im][1], a[im][2], a[im][3],
                        bA + SWZ_OFF(row, chunk));
            }
            uint32_t br[4][4];
#pragma unroll
            for (int jn = 0; jn < 4; jn++) {
                int nrow  = no + jn * 16 + (lane & 7) + (((lane >> 3) & 1) << 3);
                int chunk = ks * 2 + (lane >> 4);
                ldsm_x4(br[jn][0], br[jn][1], br[jn][2], br[jn][3],
                        bB + SWZ_OFF(nrow, chunk));
            }
#pragma unroll
            for (int im = 0; im < 2; im++)
#pragma unroll
                for (int jn = 0; jn < 4; jn++) {
                    mma16816(acc[im][jn * 2 + 0], a[im], br[jn][0], br[jn][2]);
                    mma16816(acc[im][jn * 2 + 1], a[im], br[jn][1], br[jn][3]);
                }
        }
        __syncthreads();
    }

    // epilogue: ReLU + store
#pragma unroll
    for (int im = 0; im < 2; im++) {
        int row0 = m0 + mo + im * 16 + (lane >> 2);
#pragma unroll
        for (int j = 0; j < 8; j++) {
            int col = no + j * 8 + (lane & 3) * 2;
            float* c = acc[im][j];
            if (row0 < num_ent) {
                float2 v = make_float2(fmaxf(c[0], 0.f), fmaxf(c[1], 0.f));
                *(float2*)(out + (size_t)row0 * HID + col) = v;
            }
            if (row0 + 8 < num_ent) {
                float2 v = make_float2(fmaxf(c[2], 0.f), fmaxf(c[3], 0.f));
                *(float2*)(out + (size_t)(row0 + 8) * HID + col) = v;
            }
        }
    }
}

// ===========================================================================
// Inputs: 0 local_entity(unused) 1 heads 2 tails 3 rels 4 val
//         5 rel_features[R,128] 6 W[128,128] 7 b[128]  -> out f32 [num_ent,128]
// ===========================================================================
extern "C" void kernel_launch(void* const* d_in, const int* in_sizes, int n_in,
                              void* d_out, int out_size)
{
    const int*   heads = (const int*)  d_in[1];
    const int*   tails = (const int*)  d_in[2];
    const int*   rels  = (const int*)  d_in[3];
    const float* val   = (const float*)d_in[4];
    const float* rel_f = (const float*)d_in[5];
    const float* W     = (const float*)d_in[6];
    const float* b     = (const float*)d_in[7];
    float*       out   = (float*)d_out;

    const int E       = in_sizes[1];
    const int R       = in_sizes[5] / HID;
    const int num_ent = out_size / HID;
    const int mtiles  = (num_ent + 127) / 128;

    cudaFuncSetAttribute(gemm_kernel,
                         cudaFuncAttributeMaxDynamicSharedMemorySize, SMEM_TOT);

    zero_wtrans_kernel<<<16 + 2048, 256>>>(W);
    transform_kernel<<<(R + 7) / 8, 256>>>(rel_f, b, R);
    const int fillBlocks = (E / 4 + 1 + 255) / 256;
    fill_ttrans_kernel<<<256 + fillBlocks, 256>>>(heads, tails, rels, val, E, R);
    gemm_kernel<<<mtiles, 256, SMEM_TOT>>>(out, num_ent);
}